// round 15
// baseline (speedup 1.0000x reference)
#include <cuda_runtime.h>
#include <cuda_bf16.h>
#include <stdint.h>
#include <math.h>

// ---------------- problem constants ----------------
#define LL    2048
#define LTXT  512
#define LIMG  1536
#define DIM   3072
#define NH    24
#define DH    128
#define MLPD  12288

// ---------------- scratch ----------------
__device__ __nv_bfloat16 g_xmh[(size_t)LL * DIM];
__device__ __nv_bfloat16 g_qh [(size_t)NH * LL * DH];
__device__ __nv_bfloat16 g_kh [(size_t)NH * LL * DH];
__device__ __nv_bfloat16 g_vth[(size_t)NH * DH * LL];   // [h][dh][l]
__device__ __nv_bfloat16 g_ath[(size_t)LL * DIM];
__device__ float         g_part[(size_t)4 * LL * DIM];  // split-K partials
__device__ float         g_resid[(size_t)LL * DIM];
__device__ __nv_bfloat16 g_mih[(size_t)LL * DIM];
__device__ __nv_bfloat16 g_mhh[(size_t)LL * MLPD];

// ---------------- helpers ----------------
template<int NW>
__device__ __forceinline__ float blk_sum(float v, float* sh) {
    #pragma unroll
    for (int o = 16; o; o >>= 1) v += __shfl_down_sync(0xffffffffu, v, o);
    int lane = threadIdx.x & 31, w = threadIdx.x >> 5;
    if (lane == 0) sh[w] = v;
    __syncthreads();
    if (threadIdx.x == 0) {
        float r = 0.f;
        #pragma unroll
        for (int i = 0; i < NW; i++) r += sh[i];
        sh[0] = r;
    }
    __syncthreads();
    float r = sh[0];
    __syncthreads();
    return r;
}

__device__ __forceinline__ void mma_bf16(float d[4], const uint32_t a[4],
                                         const uint32_t b[2]) {
    asm volatile(
        "mma.sync.aligned.m16n8k16.row.col.f32.bf16.bf16.f32 "
        "{%0,%1,%2,%3},{%4,%5,%6,%7},{%8,%9},{%0,%1,%2,%3};"
        : "+f"(d[0]), "+f"(d[1]), "+f"(d[2]), "+f"(d[3])
        : "r"(a[0]), "r"(a[1]), "r"(a[2]), "r"(a[3]), "r"(b[0]), "r"(b[1]));
}

__device__ __forceinline__ void ldsm4(uint32_t r[4], uint32_t addr) {
    asm volatile("ldmatrix.sync.aligned.m8n8.x4.shared.b16 {%0,%1,%2,%3}, [%4];"
                 : "=r"(r[0]), "=r"(r[1]), "=r"(r[2]), "=r"(r[3]) : "r"(addr));
}

__device__ __forceinline__ void cpa(uint32_t d, const void* s) {
    asm volatile("cp.async.cg.shared.global [%0], [%1], 16;" :: "r"(d), "l"(s));
}

__device__ __forceinline__ float ex2(float x) {
    float y;
    asm("ex2.approx.ftz.f32 %0, %1;" : "=f"(y) : "f"(x));
    return y;
}

__device__ __forceinline__ float rcp(float x) {
    float y;
    asm("rcp.approx.ftz.f32 %0, %1;" : "=f"(y) : "f"(x));
    return y;
}

// gelu(tanh approx) via sigmoid identity: 0.5x(1+tanh(z)) = x * sigmoid(2z)
__device__ __forceinline__ float fast_gelu(float x) {
    const float A = -2.3021185432f;    // -2 * 0.7978845608 * log2(e)
    const float B = -0.1029559112f;    // -2 * 0.0356774081 * log2(e)
    return x * rcp(1.f + ex2(x * (A + B * x * x)));
}

__device__ __forceinline__ uint32_t packbf(float a, float b) {
    __nv_bfloat162 t(__float2bfloat16(a), __float2bfloat16(b));
    return *reinterpret_cast<uint32_t*>(&t);
}

// ================= GEMM: C = alpha * A(bf16) @ B(fp32 wt->bf16)^T (+bias) ====
// A [M,K] bf16 (cp.async, 3-stage). B [N,K] fp32, converted in-loop.
// OUT: 0 fp32 C; 1 bf16 Ch (+gelu if ACT); 2 fused QKV epilogue
//      (bias + RMSNorm(q,k) + qknorm + RoPE + v-transpose, writes qo/ko/vo).
// Blocks with m0>=mswitch use Bw2/bias2. Split-K via blockIdx.z.
// smem: A stages @0,10240,20480; B stages @30720,40960. Total 51200 B.
template<int OUT, int ACT>
__global__ __launch_bounds__(256, 2)
void gemm_wf(const __nv_bfloat16* __restrict__ Ah,
             const float* __restrict__ Bw, const float* __restrict__ Bw2,
             float* __restrict__ C, __nv_bfloat16* __restrict__ Ch,
             const float* __restrict__ bias, const float* __restrict__ bias2,
             int mswitch, int K, int lda, int ldb, int ldc,
             long long sA, long long sB, long long sC, float alpha,
             const float* __restrict__ pe,
             const float* __restrict__ wqk_t, const float* __restrict__ wqk_i,
             __nv_bfloat16* __restrict__ qo, __nv_bfloat16* __restrict__ ko,
             __nv_bfloat16* __restrict__ vo)
{
    extern __shared__ __align__(128) char smem[];
    const int tid = threadIdx.x;
    const int lane = tid & 31;
    const int warp = tid >> 5;
    const int wm = (warp >> 2) * 64;
    const int wn = (warp & 3) * 32;

    const int m0 = blockIdx.y * 128;
    const int n0 = blockIdx.x * 128;

    const float* Bsel = Bw;
    if (Bw2 && m0 >= mswitch) { Bsel = Bw2; bias = bias2; }
    Ah   += sA * blockIdx.z;
    Bsel += sB * blockIdx.z;
    if (OUT == 0) C  += sC * blockIdx.z;
    if (OUT == 1) Ch += sC * blockIdx.z;

    const uint32_t sbase = (uint32_t)__cvta_generic_to_shared(smem);

    float acc[4][4][4];
    #pragma unroll
    for (int i = 0; i < 4; i++)
        #pragma unroll
        for (int j = 0; j < 4; j++) {
            acc[i][j][0] = 0.f; acc[i][j][1] = 0.f;
            acc[i][j][2] = 0.f; acc[i][j][3] = 0.f;
        }

    const int NC = K >> 5;   // KT=32
    float4 rb[4];

    // prologue: A chunks 0,1 via cp.async
    #pragma unroll
    for (int p = 0; p < 2; p++) {
        #pragma unroll
        for (int i = 0; i < 2; i++) {
            int s = tid + i * 256;
            int row = s >> 2, cc = (s & 3) << 3;
            cpa(sbase + (uint32_t)p * 10240u + (uint32_t)(row * 40 + cc) * 2u,
                &Ah[(long long)(m0 + row) * lda + p * 32 + cc]);
        }
        asm volatile("cp.async.commit_group;" ::: "memory");
    }
    // B chunk 0 -> regs -> smem stage 0
    #pragma unroll
    for (int i = 0; i < 4; i++) {
        int s = tid + i * 256;
        int row = s >> 3, cc = (s & 7) << 2;
        rb[i] = *reinterpret_cast<const float4*>(&Bsel[(long long)(n0 + row) * ldb + cc]);
    }
    #pragma unroll
    for (int i = 0; i < 4; i++) {
        int s = tid + i * 256;
        int row = s >> 3, cc = (s & 7) << 2;
        uint2 pk;
        pk.x = packbf(rb[i].x, rb[i].y);
        pk.y = packbf(rb[i].z, rb[i].w);
        *reinterpret_cast<uint2*>(smem + 30720 + (row * 40 + cc) * 2) = pk;
    }
    if (NC > 1) {
        #pragma unroll
        for (int i = 0; i < 4; i++) {
            int s = tid + i * 256;
            int row = s >> 3, cc = (s & 7) << 2;
            rb[i] = *reinterpret_cast<const float4*>(
                &Bsel[(long long)(n0 + row) * ldb + 32 + cc]);
        }
    }
    asm volatile("cp.async.wait_group 1;" ::: "memory");
    __syncthreads();

    for (int c = 0; c < NC; c++) {
        if (c + 2 < NC) {
            const int cc2 = c + 2;
            #pragma unroll
            for (int i = 0; i < 2; i++) {
                int s = tid + i * 256;
                int row = s >> 2, ccx = (s & 3) << 3;
                cpa(sbase + (uint32_t)(cc2 % 3) * 10240u
                        + (uint32_t)(row * 40 + ccx) * 2u,
                    &Ah[(long long)(m0 + row) * lda + cc2 * 32 + ccx]);
            }
        }
        asm volatile("cp.async.commit_group;" ::: "memory");

        // compute one 32-K chunk
        {
            const uint32_t sA_ = sbase + (uint32_t)(c % 3) * 10240u;
            const uint32_t sB_ = sbase + 30720u + (uint32_t)(c & 1) * 10240u;
            const int aRow = lane & 15;
            const int aK   = (lane & 16) ? 8 : 0;
            const int bRow = (lane & 7) + ((lane & 16) ? 8 : 0);
            const int bK   = (lane & 8) ? 8 : 0;
            #pragma unroll
            for (int kh = 0; kh < 32; kh += 16) {
                uint32_t ah[4][4];
                uint32_t bh[2][4];
                #pragma unroll
                for (int mt = 0; mt < 4; mt++) {
                    uint32_t off = (uint32_t)((wm + mt * 16 + aRow) * 40 + kh + aK) * 2u;
                    ldsm4(ah[mt], sA_ + off);
                }
                #pragma unroll
                for (int pr = 0; pr < 2; pr++) {
                    uint32_t off = (uint32_t)((wn + pr * 16 + bRow) * 40 + kh + bK) * 2u;
                    ldsm4(bh[pr], sB_ + off);
                }
                #pragma unroll
                for (int mt = 0; mt < 4; mt++)
                    #pragma unroll
                    for (int nt = 0; nt < 4; nt++)
                        mma_bf16(acc[mt][nt], ah[mt], &bh[nt >> 1][(nt & 1) * 2]);
            }
        }
        __syncthreads();

        if (c + 1 < NC) {
            #pragma unroll
            for (int i = 0; i < 4; i++) {
                int s = tid + i * 256;
                int row = s >> 3, cc = (s & 7) << 2;
                uint2 pk;
                pk.x = packbf(rb[i].x, rb[i].y);
                pk.y = packbf(rb[i].z, rb[i].w);
                *reinterpret_cast<uint2*>(
                    smem + 30720 + ((c + 1) & 1) * 10240 + (row * 40 + cc) * 2) = pk;
            }
            if (c + 2 < NC) {
                #pragma unroll
                for (int i = 0; i < 4; i++) {
                    int s = tid + i * 256;
                    int row = s >> 3, cc = (s & 7) << 2;
                    rb[i] = *reinterpret_cast<const float4*>(
                        &Bsel[(long long)(n0 + row) * ldb + (c + 2) * 32 + cc]);
                }
            }
            asm volatile("cp.async.wait_group 1;" ::: "memory");
            __syncthreads();
        }
    }

    // ---------------- epilogue ----------------
    const int crow = lane >> 2;
    const int ccol = (lane & 3) << 1;

    #pragma unroll
    for (int mt = 0; mt < 4; mt++)
        #pragma unroll
        for (int nt = 0; nt < 4; nt++) {
            const int gn = n0 + wn + nt * 8 + ccol;
            #pragma unroll
            for (int half = 0; half < 2; half++) {
                acc[mt][nt][half * 2 + 0] =
                    acc[mt][nt][half * 2 + 0] * alpha + (bias ? bias[gn] : 0.f);
                acc[mt][nt][half * 2 + 1] =
                    acc[mt][nt][half * 2 + 1] * alpha + (bias ? bias[gn + 1] : 0.f);
            }
        }

    if (OUT == 2) {
        const int type = n0 / DIM;            // 0=q 1=k 2=v
        const int hh   = (n0 % DIM) / DH;     // head index
        if (type == 2) {
            #pragma unroll
            for (int mt = 0; mt < 4; mt++)
                #pragma unroll
                for (int nt = 0; nt < 4; nt++) {
                    const int d = wn + nt * 8 + ccol;
                    #pragma unroll
                    for (int half = 0; half < 2; half++) {
                        const int gm = m0 + wm + mt * 16 + crow + half * 8;
                        vo[((size_t)hh * DH + d) * LL + gm] =
                            __float2bfloat16(acc[mt][nt][half * 2 + 0]);
                        vo[((size_t)hh * DH + d + 1) * LL + gm] =
                            __float2bfloat16(acc[mt][nt][half * 2 + 1]);
                    }
                }
        } else {
            float* rows = reinterpret_cast<float*>(smem);   // [4][128]
            __syncthreads();
            #pragma unroll
            for (int mt = 0; mt < 4; mt++) {
                #pragma unroll
                for (int half = 0; half < 2; half++) {
                    float ssum = 0.f;
                    #pragma unroll
                    for (int nt = 0; nt < 4; nt++) {
                        float a0 = acc[mt][nt][half * 2 + 0];
                        float a1 = acc[mt][nt][half * 2 + 1];
                        ssum += a0 * a0 + a1 * a1;
                    }
                    ssum += __shfl_xor_sync(0xffffffffu, ssum, 1);
                    ssum += __shfl_xor_sync(0xffffffffu, ssum, 2);
                    if ((lane & 3) == 0) {
                        const int lm = wm + mt * 16 + crow + half * 8;
                        rows[(warp & 3) * 128 + lm] = ssum;
                    }
                }
            }
            __syncthreads();
            __nv_bfloat16* dst = (type == 0) ? qo : ko;
            #pragma unroll
            for (int mt = 0; mt < 4; mt++) {
                #pragma unroll
                for (int half = 0; half < 2; half++) {
                    const int lm = wm + mt * 16 + crow + half * 8;
                    const int gm = m0 + lm;
                    const float tot = rows[lm] + rows[128 + lm]
                                    + rows[256 + lm] + rows[384 + lm];
                    const float rs = rsqrtf(tot * (1.f / DH) + 1e-6f);
                    const float* wn_ = (gm < LTXT) ? wqk_t : wqk_i;
                    #pragma unroll
                    for (int nt = 0; nt < 4; nt++) {
                        const int d = wn + nt * 8 + ccol;     // even
                        float ve = acc[mt][nt][half * 2 + 0] * rs * wn_[d];
                        float vodd = acc[mt][nt][half * 2 + 1] * rs * wn_[d + 1];
                        const float cth = pe[(size_t)gm * 256 + (d >> 1) * 4 + 0];
                        const float sth = pe[(size_t)gm * 256 + (d >> 1) * 4 + 2];
                        float r0 = ve * cth - vodd * sth;
                        float r1 = ve * sth + vodd * cth;
                        *reinterpret_cast<__nv_bfloat162*>(
                            &dst[((size_t)hh * LL + gm) * DH + d]) =
                            __nv_bfloat162(__float2bfloat16(r0), __float2bfloat16(r1));
                    }
                }
            }
        }
    } else {
        #pragma unroll
        for (int mt = 0; mt < 4; mt++) {
            #pragma unroll
            for (int nt = 0; nt < 4; nt++) {
                const int gn = n0 + wn + nt * 8 + ccol;
                #pragma unroll
                for (int half = 0; half < 2; half++) {
                    const int gm = m0 + wm + mt * 16 + crow + half * 8;
                    float v0 = acc[mt][nt][half * 2 + 0];
                    float v1 = acc[mt][nt][half * 2 + 1];
                    if (ACT == 1) {
                        v0 = fast_gelu(v0);
                        v1 = fast_gelu(v1);
                    }
                    const long long ci = (long long)gm * ldc + gn;
                    if (OUT == 0) {
                        *reinterpret_cast<float2*>(&C[ci]) = make_float2(v0, v1);
                    } else {
                        *reinterpret_cast<__nv_bfloat162*>(&Ch[ci]) =
                            __nv_bfloat162(__float2bfloat16(v0), __float2bfloat16(v1));
                    }
                }
            }
        }
    }
}

// ================= flash attention ==========================================
__global__ __launch_bounds__(128, 2)
void flash_kernel(const __nv_bfloat16* __restrict__ qg_,
                  const __nv_bfloat16* __restrict__ kg_,
                  const __nv_bfloat16* __restrict__ vg_,
                  __nv_bfloat16* __restrict__ o_)
{
    extern __shared__ __align__(128) char fsm[];
    const int tid = threadIdx.x, lane = tid & 31, warp = tid >> 5;
    const int qb = blockIdx.x, h = blockIdx.y;
    const char* qg = (const char*)(qg_ + ((size_t)h * LL + (size_t)qb * 64) * DH);
    const char* kg = (const char*)(kg_ + (size_t)h * LL * DH);
    const char* vg = (const char*)(vg_ + (size_t)h * DH * LL);
    const uint32_t sq = (uint32_t)__cvta_generic_to_shared(fsm);
    const uint32_t sk = sq + 17408u;
    const uint32_t sv = sq + 52224u;

    const int aRow = lane & 15;
    const int aK   = (lane & 16) ? 8 : 0;
    const int bRow = (lane & 7) + ((lane & 16) ? 8 : 0);
    const int bK   = (lane & 8) ? 8 : 0;
    const int g = lane >> 2, t4 = lane & 3;

    #pragma unroll
    for (int i = 0; i < 8; i++) {
        int idx = tid + i * 128;
        int row = idx >> 4, cb = (idx & 15) * 16;
        cpa(sq + (uint32_t)(row * 272 + cb), qg + row * 256 + cb);
    }
    asm volatile("cp.async.commit_group;" ::: "memory");

    float mv0 = -1e30f, mv1 = -1e30f, l0 = 0.f, l1 = 0.f;
    float oa[16][4];
    #pragma unroll
    for (int nt = 0; nt < 16; nt++) {
        oa[nt][0] = 0.f; oa[nt][1] = 0.f; oa[nt][2] = 0.f; oa[nt][3] = 0.f;
    }

    const float Cc = 0.12751781429348323f;  // (1/sqrt(128)) * log2(e)

    for (int kb = 0; kb < 16; kb++) {
        __syncthreads();
        #pragma unroll
        for (int i = 0; i < 16; i++) {
            int idx = tid + i * 128;
            int row = idx >> 4, cb = (idx & 15) * 16;
            cpa(sk + (uint32_t)(row * 272 + cb),
                kg + (size_t)(kb * 128 + row) * 256 + cb);
            cpa(sv + (uint32_t)(row * 272 + cb),
                vg + (size_t)row * 4096 + kb * 256 + cb);
        }
        asm volatile("cp.async.commit_group;" ::: "memory");
        asm volatile("cp.async.wait_group 0;" ::: "memory");
        __syncthreads();

        float sa[16][4];
        #pragma unroll
        for (int nt = 0; nt < 16; nt++) {
            sa[nt][0] = 0.f; sa[nt][1] = 0.f; sa[nt][2] = 0.f; sa[nt][3] = 0.f;
        }
        #pragma unroll
        for (int ks = 0; ks < 8; ks++) {
            uint32_t qf[4];
            ldsm4(qf, sq + (uint32_t)((warp * 16 + aRow) * 136 + ks * 16 + aK) * 2u);
            #pragma unroll
            for (int pr = 0; pr < 8; pr++) {
                uint32_t bf[4];
                ldsm4(bf, sk + (uint32_t)((pr * 16 + bRow) * 136 + ks * 16 + bK) * 2u);
                mma_bf16(sa[2 * pr],     qf, &bf[0]);
                mma_bf16(sa[2 * pr + 1], qf, &bf[2]);
            }
        }

        float rm0 = -1e30f, rm1 = -1e30f;
        #pragma unroll
        for (int nt = 0; nt < 16; nt++) {
            rm0 = fmaxf(rm0, fmaxf(sa[nt][0], sa[nt][1]));
            rm1 = fmaxf(rm1, fmaxf(sa[nt][2], sa[nt][3]));
        }
        rm0 = fmaxf(rm0, __shfl_xor_sync(0xffffffffu, rm0, 1));
        rm0 = fmaxf(rm0, __shfl_xor_sync(0xffffffffu, rm0, 2));
        rm1 = fmaxf(rm1, __shfl_xor_sync(0xffffffffu, rm1, 1));
        rm1 = fmaxf(rm1, __shfl_xor_sync(0xffffffffu, rm1, 2));
        const float mn0 = fmaxf(mv0, rm0), mn1 = fmaxf(mv1, rm1);
        const float r0 = ex2((mv0 - mn0) * Cc), r1 = ex2((mv1 - mn1) * Cc);
        mv0 = mn0; mv1 = mn1;

        float s0 = 0.f, s1 = 0.f;
        uint32_t pf[16], pg[16];
        #pragma unroll
        for (int nt = 0; nt < 16; nt++) {
            float p0 = ex2((sa[nt][0] - mn0) * Cc);
            float p1 = ex2((sa[nt][1] - mn0) * Cc);
            float p2 = ex2((sa[nt][2] - mn1) * Cc);
            float p3 = ex2((sa[nt][3] - mn1) * Cc);
            s0 += p0 + p1; s1 += p2 + p3;
            pf[nt] = packbf(p0, p1);
            pg[nt] = packbf(p2, p3);
        }
        s0 += __shfl_xor_sync(0xffffffffu, s0, 1);
        s0 += __shfl_xor_sync(0xffffffffu, s0, 2);
        s1 += __shfl_xor_sync(0xffffffffu, s1, 1);
        s1 += __shfl_xor_sync(0xffffffffu, s1, 2);
        l0 = l0 * r0 + s0;
        l1 = l1 * r1 + s1;
        #pragma unroll
        for (int nt = 0; nt < 16; nt++) {
            oa[nt][0] *= r0; oa[nt][1] *= r0;
            oa[nt][2] *= r1; oa[nt][3] *= r1;
        }

        #pragma unroll
        for (int ks = 0; ks < 8; ks++) {
            uint32_t af[4];
            af[0] = pf[2 * ks];     af[1] = pg[2 * ks];
            af[2] = pf[2 * ks + 1]; af[3] = pg[2 * ks + 1];
            #pragma unroll
            for (int pr = 0; pr < 8; pr++) {
                uint32_t bf[4];
                ldsm4(bf, sv + (uint32_t)((pr * 16 + bRow) * 136 + ks * 16 + bK) * 2u);
                mma_bf16(oa[2 * pr],     af, &bf[0]);
                mma_bf16(oa[2 * pr + 1], af, &bf[2]);
            }
        }
    }

    const float i0 = 1.f / l0, i1 = 1.f / l1;
    const int row0 = qb * 64 + warp * 16 + g;
    #pragma unroll
    for (int nt = 0; nt < 16; nt++) {
        const int col = h * DH + nt * 8 + 2 * t4;
        *reinterpret_cast<__nv_bfloat162*>(&o_[(size_t)row0 * DIM + col]) =
            __nv_bfloat162(__float2bfloat16(oa[nt][0] * i0),
                           __float2bfloat16(oa[nt][1] * i0));
        *reinterpret_cast<__nv_bfloat162*>(&o_[(size_t)(row0 + 8) * DIM + col]) =
            __nv_bfloat162(__float2bfloat16(oa[nt][2] * i1),
                           __float2bfloat16(oa[nt][3] * i1));
    }
}

// ---------------- LN + adaLN modulation -> bf16 ----------------
__global__ __launch_bounds__(256)
void lnmod_attn_kernel(const float* __restrict__ img_e, const float* __restrict__ txt_e,
                       const float* __restrict__ i_sc, const float* __restrict__ i_sh,
                       const float* __restrict__ t_sc, const float* __restrict__ t_sh,
                       __nv_bfloat16* __restrict__ oh)
{
    const int row = blockIdx.x;
    const bool is_txt = row < LTXT;
    const float* x  = is_txt ? txt_e + (size_t)row * DIM : img_e + (size_t)(row - LTXT) * DIM;
    const float* sc = is_txt ? t_sc : i_sc;
    const float* sh = is_txt ? t_sh : i_sh;
    __shared__ float red[8];
    const int tid = threadIdx.x;
    float v[12];
    float s = 0.f, ss = 0.f;
    #pragma unroll
    for (int i = 0; i < 12; i++) {
        float a = x[tid + i * 256];
        v[i] = a; s += a; ss += a * a;
    }
    s  = blk_sum<8>(s,  red);
    ss = blk_sum<8>(ss, red);
    const float m   = s * (1.f / DIM);
    const float var = ss * (1.f / DIM) - m * m;
    const float rs  = rsqrtf(var + 1e-6f);
    #pragma unroll
    for (int i = 0; i < 12; i++) {
        const int c = tid + i * 256;
        oh[(size_t)row * DIM + c] =
            __float2bfloat16((1.f + sc[c]) * (v[i] - m) * rs + sh[c]);
    }
}

// ---- attn residual (gated, 4-way split-K reduce + bias) + LN + MLP mod ----
__global__ __launch_bounds__(256)
void resid_lnmod_kernel(const float* __restrict__ part, const float* __restrict__ proj_b,
                        const float* __restrict__ img_e, const float* __restrict__ txt_e,
                        const float* __restrict__ i_gate, const float* __restrict__ t_gate,
                        const float* __restrict__ i_sc, const float* __restrict__ i_sh,
                        const float* __restrict__ t_sc, const float* __restrict__ t_sh,
                        float* __restrict__ resid, __nv_bfloat16* __restrict__ mih)
{
    const int row = blockIdx.x;
    const bool is_txt = row < LTXT;
    const float* e  = is_txt ? txt_e + (size_t)row * DIM : img_e + (size_t)(row - LTXT) * DIM;
    const float* g  = is_txt ? t_gate : i_gate;
    const float* sc = is_txt ? t_sc : i_sc;
    const float* sh = is_txt ? t_sh : i_sh;
    __shared__ float red[8];
    const int tid = threadIdx.x;
    const size_t PS = (size_t)LL * DIM;
    float r[12];
    float s = 0.f, ss = 0.f;
    #pragma unroll
    for (int i = 0; i < 12; i++) {
        const int c = tid + i * 256;
        const size_t idx = (size_t)row * DIM + c;
        float p = part[idx] + part[PS + idx] + part[2 * PS + idx] + part[3 * PS + idx]
                + proj_b[c];
        float x = e[c] + g[c] * p;
        r[i] = x; s += x; ss += x * x;
        resid[idx] = x;
    }
    s  = blk_sum<8>(s,  red);
    ss = blk_sum<8>(ss, red);
    const float m   = s * (1.f / DIM);
    const float var = ss * (1.f / DIM) - m * m;
    const float rs  = rsqrtf(var + 1e-6f);
    #pragma unroll
    for (int i = 0; i < 12; i++) {
        const int c = tid + i * 256;
        mih[(size_t)row * DIM + c] =
            __float2bfloat16((1.f + sc[c]) * (r[i] - m) * rs + sh[c]);
    }
}

// ---- final gated residual (4-way split-K reduce + bias) -> d_out ----
__global__ __launch_bounds__(256)
void final_kernel(const float* __restrict__ part,
                  const float* __restrict__ t_b2, const float* __restrict__ i_b2,
                  const float* __restrict__ resid,
                  const float* __restrict__ i_gate, const float* __restrict__ t_gate,
                  float* __restrict__ out)
{
    const int row = blockIdx.x;
    const int tid = threadIdx.x;
    const bool is_txt = row < LTXT;
    const float* g  = is_txt ? t_gate : i_gate;
    const float* b2 = is_txt ? t_b2 : i_b2;
    const size_t PS = (size_t)LL * DIM;
    float* dst = is_txt ? out + (size_t)LIMG * DIM + (size_t)row * DIM
                        : out + (size_t)(row - LTXT) * DIM;
    #pragma unroll
    for (int i = 0; i < 12; i++) {
        const int c = tid + i * 256;
        const size_t idx = (size_t)row * DIM + c;
        float mlp = part[idx] + part[PS + idx] + part[2 * PS + idx]
                  + part[3 * PS + idx] + b2[c];
        dst[c] = resid[idx] + g[c] * mlp;
    }
}

// ---------------- launch ----------------
extern "C" void kernel_launch(void* const* d_in, const int* in_sizes, int n_in,
                              void* d_out, int out_size)
{
    const float* img_e       = (const float*)d_in[0];
    const float* txt_e       = (const float*)d_in[1];
    const float* pe          = (const float*)d_in[2];
    const float* i_attn_sc   = (const float*)d_in[3];
    const float* i_attn_sh   = (const float*)d_in[4];
    const float* i_attn_gate = (const float*)d_in[5];
    const float* i_mlp_sc    = (const float*)d_in[6];
    const float* i_mlp_sh    = (const float*)d_in[7];
    const float* i_mlp_gate  = (const float*)d_in[8];
    const float* t_attn_sc   = (const float*)d_in[9];
    const float* t_attn_sh   = (const float*)d_in[10];
    const float* t_attn_gate = (const float*)d_in[11];
    const float* t_mlp_sc    = (const float*)d_in[12];
    const float* t_mlp_sh    = (const float*)d_in[13];
    const float* t_mlp_gate  = (const float*)d_in[14];
    const float* i_qkv_w     = (const float*)d_in[15];
    const float* i_qkv_b     = (const float*)d_in[16];
    const float* i_qknorm    = (const float*)d_in[17];
    const float* t_qkv_w     = (const float*)d_in[18];
    const float* t_qkv_b     = (const float*)d_in[19];
    const float* t_qknorm    = (const float*)d_in[20];
    const float* proj_w      = (const float*)d_in[21];
    const float* proj_b      = (const float*)d_in[22];
    const float* i_mlp_w1    = (const float*)d_in[23];
    const float* i_mlp_b1    = (const float*)d_in[24];
    const float* i_mlp_w2    = (const float*)d_in[25];
    const float* i_mlp_b2    = (const float*)d_in[26];
    const float* t_mlp_w1    = (const float*)d_in[27];
    const float* t_mlp_b1    = (const float*)d_in[28];
    const float* t_mlp_w2    = (const float*)d_in[29];
    const float* t_mlp_b2    = (const float*)d_in[30];
    // d_in[31] = mask (all-true; unused)

    __nv_bfloat16 *xmh, *qh, *kh, *vth, *ath, *mih, *mhh;
    float *part, *resid;
    cudaGetSymbolAddress((void**)&xmh,   g_xmh);
    cudaGetSymbolAddress((void**)&qh,    g_qh);
    cudaGetSymbolAddress((void**)&kh,    g_kh);
    cudaGetSymbolAddress((void**)&vth,   g_vth);
    cudaGetSymbolAddress((void**)&ath,   g_ath);
    cudaGetSymbolAddress((void**)&part,  g_part);
    cudaGetSymbolAddress((void**)&resid, g_resid);
    cudaGetSymbolAddress((void**)&mih,   g_mih);
    cudaGetSymbolAddress((void**)&mhh,   g_mhh);

    const int GSMEM = 51200;
    const int FSMEM = 87040;
    cudaFuncSetAttribute(gemm_wf<0, 0>, cudaFuncAttributeMaxDynamicSharedMemorySize, GSMEM);
    cudaFuncSetAttribute(gemm_wf<1, 1>, cudaFuncAttributeMaxDynamicSharedMemorySize, GSMEM);
    cudaFuncSetAttribute(gemm_wf<2, 0>, cudaFuncAttributeMaxDynamicSharedMemorySize, GSMEM);
    cudaFuncSetAttribute(flash_kernel,  cudaFuncAttributeMaxDynamicSharedMemorySize, FSMEM);

    // 1) LN + attention modulation -> bf16
    lnmod_attn_kernel<<<LL, 256>>>(img_e, txt_e, i_attn_sc, i_attn_sh,
                                   t_attn_sc, t_attn_sh, xmh);

    // 2) QKV GEMM with fused bias + RMSNorm + RoPE + v-transpose epilogue
    gemm_wf<2, 0><<<dim3(3 * DIM / 128, LL / 128, 1), 256, GSMEM>>>(
        xmh, t_qkv_w, i_qkv_w, nullptr, nullptr, t_qkv_b, i_qkv_b,
        LTXT, DIM, DIM, DIM, 0, 0, 0, 0, 1.f,
        pe, t_qknorm, i_qknorm, qh, kh, vth);

    // 3) fused flash attention -> bf16 ath [l, h*DH+dh]
    flash_kernel<<<dim3(LL / 64, NH), 128, FSMEM>>>(qh, kh, vth, ath);

    // 4) shared projection, split-K=4 -> fp32 partials
    gemm_wf<0, 0><<<dim3(DIM / 128, LL / 128, 4), 256, GSMEM>>>(
        ath, proj_w, nullptr, part, nullptr, nullptr, nullptr,
        0, DIM / 4, DIM, DIM, DIM,
        (long long)(DIM / 4), (long long)(DIM / 4), (long long)LL * DIM, 1.f,
        nullptr, nullptr, nullptr, nullptr, nullptr, nullptr);

    // 5) gated attn residual (reduce partials + bias) + LN + MLP modulation
    resid_lnmod_kernel<<<LL, 256>>>(part, proj_b, img_e, txt_e,
                                    i_attn_gate, t_attn_gate,
                                    i_mlp_sc, i_mlp_sh, t_mlp_sc, t_mlp_sh,
                                    resid, mih);

    // 6) MLP up (merged, bias+gelu fused) -> bf16 h
    gemm_wf<1, 1><<<dim3(MLPD / 128, LL / 128, 1), 256, GSMEM>>>(
        mih, t_mlp_w1, i_mlp_w1, nullptr, mhh, t_mlp_b1, i_mlp_b1,
        LTXT, DIM, DIM, DIM, MLPD, 0, 0, 0, 1.f,
        nullptr, nullptr, nullptr, nullptr, nullptr, nullptr);

    // 7) MLP down (merged, split-K=4) -> fp32 partials
    gemm_wf<0, 0><<<dim3(DIM / 128, LL / 128, 4), 256, GSMEM>>>(
        mhh, t_mlp_w2, i_mlp_w2, part, nullptr, nullptr, nullptr,
        LTXT, MLPD / 4, MLPD, MLPD, DIM,
        (long long)(MLPD / 4), (long long)(MLPD / 4), (long long)LL * DIM, 1.f,
        nullptr, nullptr, nullptr, nullptr, nullptr, nullptr);

    // 8) final gated residual (reduce partials + bias) -> output
    final_kernel<<<LL, 256>>>(part, t_mlp_b2, i_mlp_b2, resid,
                              i_mlp_gate, t_mlp_gate, (float*)d_out);
}

// round 16
// speedup vs baseline: 1.0100x; 1.0100x over previous
#include <cuda_runtime.h>
#include <cuda_bf16.h>
#include <stdint.h>
#include <math.h>

// ---------------- problem constants ----------------
#define LL    2048
#define LTXT  512
#define LIMG  1536
#define DIM   3072
#define NH    24
#define DH    128
#define MLPD  12288

// ---------------- scratch ----------------
__device__ __nv_bfloat16 g_xmh[(size_t)LL * DIM];
__device__ __nv_bfloat16 g_qh [(size_t)NH * LL * DH];
__device__ __nv_bfloat16 g_kh [(size_t)NH * LL * DH];
__device__ __nv_bfloat16 g_vth[(size_t)NH * DH * LL];   // [h][dh][l]
__device__ __nv_bfloat16 g_ath[(size_t)LL * DIM];
__device__ float         g_part[(size_t)2 * LL * DIM];  // split-K partials (K=2)
__device__ float         g_resid[(size_t)LL * DIM];
__device__ __nv_bfloat16 g_mih[(size_t)LL * DIM];
__device__ __nv_bfloat16 g_mhh[(size_t)LL * MLPD];

// ---------------- helpers ----------------
template<int NW>
__device__ __forceinline__ float blk_sum(float v, float* sh) {
    #pragma unroll
    for (int o = 16; o; o >>= 1) v += __shfl_down_sync(0xffffffffu, v, o);
    int lane = threadIdx.x & 31, w = threadIdx.x >> 5;
    if (lane == 0) sh[w] = v;
    __syncthreads();
    if (threadIdx.x == 0) {
        float r = 0.f;
        #pragma unroll
        for (int i = 0; i < NW; i++) r += sh[i];
        sh[0] = r;
    }
    __syncthreads();
    float r = sh[0];
    __syncthreads();
    return r;
}

__device__ __forceinline__ void mma_bf16(float d[4], const uint32_t a[4],
                                         const uint32_t b[2]) {
    asm volatile(
        "mma.sync.aligned.m16n8k16.row.col.f32.bf16.bf16.f32 "
        "{%0,%1,%2,%3},{%4,%5,%6,%7},{%8,%9},{%0,%1,%2,%3};"
        : "+f"(d[0]), "+f"(d[1]), "+f"(d[2]), "+f"(d[3])
        : "r"(a[0]), "r"(a[1]), "r"(a[2]), "r"(a[3]), "r"(b[0]), "r"(b[1]));
}

__device__ __forceinline__ void ldsm4(uint32_t r[4], uint32_t addr) {
    asm volatile("ldmatrix.sync.aligned.m8n8.x4.shared.b16 {%0,%1,%2,%3}, [%4];"
                 : "=r"(r[0]), "=r"(r[1]), "=r"(r[2]), "=r"(r[3]) : "r"(addr));
}

__device__ __forceinline__ void cpa(uint32_t d, const void* s) {
    asm volatile("cp.async.cg.shared.global [%0], [%1], 16;" :: "r"(d), "l"(s));
}

__device__ __forceinline__ float ex2(float x) {
    float y;
    asm("ex2.approx.ftz.f32 %0, %1;" : "=f"(y) : "f"(x));
    return y;
}

__device__ __forceinline__ float rcp(float x) {
    float y;
    asm("rcp.approx.ftz.f32 %0, %1;" : "=f"(y) : "f"(x));
    return y;
}

// gelu(tanh approx) via sigmoid identity: 0.5x(1+tanh(z)) = x * sigmoid(2z)
__device__ __forceinline__ float fast_gelu(float x) {
    const float A = -2.3021185432f;    // -2 * 0.7978845608 * log2(e)
    const float B = -0.1029559112f;    // -2 * 0.0356774081 * log2(e)
    return x * rcp(1.f + ex2(x * (A + B * x * x)));
}

__device__ __forceinline__ uint32_t packbf(float a, float b) {
    __nv_bfloat162 t(__float2bfloat16(a), __float2bfloat16(b));
    return *reinterpret_cast<uint32_t*>(&t);
}

// ================= GEMM: C = alpha * A(bf16) @ B(fp32 wt->bf16)^T (+bias) ====
// A [M,K] bf16 (cp.async, 3-stage). B [N,K] fp32, converted in-loop.
// OUT: 0 fp32 C; 1 bf16 Ch (+gelu if ACT); 2 fused QKV epilogue
//      (bias + RMSNorm(q,k) + qknorm + RoPE + v-transpose, writes qo/ko/vo).
// Blocks with m0>=mswitch use Bw2/bias2. Split-K via blockIdx.z.
// smem: A stages @0,10240,20480; B stages @30720,40960. Total 51200 B.
template<int OUT, int ACT>
__global__ __launch_bounds__(256, 2)
void gemm_wf(const __nv_bfloat16* __restrict__ Ah,
             const float* __restrict__ Bw, const float* __restrict__ Bw2,
             float* __restrict__ C, __nv_bfloat16* __restrict__ Ch,
             const float* __restrict__ bias, const float* __restrict__ bias2,
             int mswitch, int K, int lda, int ldb, int ldc,
             long long sA, long long sB, long long sC, float alpha,
             const float* __restrict__ pe,
             const float* __restrict__ wqk_t, const float* __restrict__ wqk_i,
             __nv_bfloat16* __restrict__ qo, __nv_bfloat16* __restrict__ ko,
             __nv_bfloat16* __restrict__ vo)
{
    extern __shared__ __align__(128) char smem[];
    const int tid = threadIdx.x;
    const int lane = tid & 31;
    const int warp = tid >> 5;
    const int wm = (warp >> 2) * 64;
    const int wn = (warp & 3) * 32;

    const int m0 = blockIdx.y * 128;
    const int n0 = blockIdx.x * 128;

    const float* Bsel = Bw;
    if (Bw2 && m0 >= mswitch) { Bsel = Bw2; bias = bias2; }
    Ah   += sA * blockIdx.z;
    Bsel += sB * blockIdx.z;
    if (OUT == 0) C  += sC * blockIdx.z;
    if (OUT == 1) Ch += sC * blockIdx.z;

    const uint32_t sbase = (uint32_t)__cvta_generic_to_shared(smem);

    float acc[4][4][4];
    #pragma unroll
    for (int i = 0; i < 4; i++)
        #pragma unroll
        for (int j = 0; j < 4; j++) {
            acc[i][j][0] = 0.f; acc[i][j][1] = 0.f;
            acc[i][j][2] = 0.f; acc[i][j][3] = 0.f;
        }

    const int NC = K >> 5;   // KT=32
    float4 rb[4];

    // prologue: A chunks 0,1 via cp.async
    #pragma unroll
    for (int p = 0; p < 2; p++) {
        #pragma unroll
        for (int i = 0; i < 2; i++) {
            int s = tid + i * 256;
            int row = s >> 2, cc = (s & 3) << 3;
            cpa(sbase + (uint32_t)p * 10240u + (uint32_t)(row * 40 + cc) * 2u,
                &Ah[(long long)(m0 + row) * lda + p * 32 + cc]);
        }
        asm volatile("cp.async.commit_group;" ::: "memory");
    }
    // B chunk 0 -> regs -> smem stage 0
    #pragma unroll
    for (int i = 0; i < 4; i++) {
        int s = tid + i * 256;
        int row = s >> 3, cc = (s & 7) << 2;
        rb[i] = *reinterpret_cast<const float4*>(&Bsel[(long long)(n0 + row) * ldb + cc]);
    }
    #pragma unroll
    for (int i = 0; i < 4; i++) {
        int s = tid + i * 256;
        int row = s >> 3, cc = (s & 7) << 2;
        uint2 pk;
        pk.x = packbf(rb[i].x, rb[i].y);
        pk.y = packbf(rb[i].z, rb[i].w);
        *reinterpret_cast<uint2*>(smem + 30720 + (row * 40 + cc) * 2) = pk;
    }
    if (NC > 1) {
        #pragma unroll
        for (int i = 0; i < 4; i++) {
            int s = tid + i * 256;
            int row = s >> 3, cc = (s & 7) << 2;
            rb[i] = *reinterpret_cast<const float4*>(
                &Bsel[(long long)(n0 + row) * ldb + 32 + cc]);
        }
    }
    asm volatile("cp.async.wait_group 1;" ::: "memory");
    __syncthreads();

    for (int c = 0; c < NC; c++) {
        if (c + 2 < NC) {
            const int cc2 = c + 2;
            #pragma unroll
            for (int i = 0; i < 2; i++) {
                int s = tid + i * 256;
                int row = s >> 2, ccx = (s & 3) << 3;
                cpa(sbase + (uint32_t)(cc2 % 3) * 10240u
                        + (uint32_t)(row * 40 + ccx) * 2u,
                    &Ah[(long long)(m0 + row) * lda + cc2 * 32 + ccx]);
            }
        }
        asm volatile("cp.async.commit_group;" ::: "memory");

        // compute one 32-K chunk
        {
            const uint32_t sA_ = sbase + (uint32_t)(c % 3) * 10240u;
            const uint32_t sB_ = sbase + 30720u + (uint32_t)(c & 1) * 10240u;
            const int aRow = lane & 15;
            const int aK   = (lane & 16) ? 8 : 0;
            const int bRow = (lane & 7) + ((lane & 16) ? 8 : 0);
            const int bK   = (lane & 8) ? 8 : 0;
            #pragma unroll
            for (int kh = 0; kh < 32; kh += 16) {
                uint32_t ah[4][4];
                uint32_t bh[2][4];
                #pragma unroll
                for (int mt = 0; mt < 4; mt++) {
                    uint32_t off = (uint32_t)((wm + mt * 16 + aRow) * 40 + kh + aK) * 2u;
                    ldsm4(ah[mt], sA_ + off);
                }
                #pragma unroll
                for (int pr = 0; pr < 2; pr++) {
                    uint32_t off = (uint32_t)((wn + pr * 16 + bRow) * 40 + kh + bK) * 2u;
                    ldsm4(bh[pr], sB_ + off);
                }
                #pragma unroll
                for (int mt = 0; mt < 4; mt++)
                    #pragma unroll
                    for (int nt = 0; nt < 4; nt++)
                        mma_bf16(acc[mt][nt], ah[mt], &bh[nt >> 1][(nt & 1) * 2]);
            }
        }
        __syncthreads();

        if (c + 1 < NC) {
            #pragma unroll
            for (int i = 0; i < 4; i++) {
                int s = tid + i * 256;
                int row = s >> 3, cc = (s & 7) << 2;
                uint2 pk;
                pk.x = packbf(rb[i].x, rb[i].y);
                pk.y = packbf(rb[i].z, rb[i].w);
                *reinterpret_cast<uint2*>(
                    smem + 30720 + ((c + 1) & 1) * 10240 + (row * 40 + cc) * 2) = pk;
            }
            if (c + 2 < NC) {
                #pragma unroll
                for (int i = 0; i < 4; i++) {
                    int s = tid + i * 256;
                    int row = s >> 3, cc = (s & 7) << 2;
                    rb[i] = *reinterpret_cast<const float4*>(
                        &Bsel[(long long)(n0 + row) * ldb + (c + 2) * 32 + cc]);
                }
            }
            asm volatile("cp.async.wait_group 1;" ::: "memory");
            __syncthreads();
        }
    }

    // ---------------- epilogue ----------------
    const int crow = lane >> 2;
    const int ccol = (lane & 3) << 1;

    #pragma unroll
    for (int mt = 0; mt < 4; mt++)
        #pragma unroll
        for (int nt = 0; nt < 4; nt++) {
            const int gn = n0 + wn + nt * 8 + ccol;
            #pragma unroll
            for (int half = 0; half < 2; half++) {
                acc[mt][nt][half * 2 + 0] =
                    acc[mt][nt][half * 2 + 0] * alpha + (bias ? bias[gn] : 0.f);
                acc[mt][nt][half * 2 + 1] =
                    acc[mt][nt][half * 2 + 1] * alpha + (bias ? bias[gn + 1] : 0.f);
            }
        }

    if (OUT == 2) {
        const int type = n0 / DIM;            // 0=q 1=k 2=v
        const int hh   = (n0 % DIM) / DH;     // head index
        if (type == 2) {
            #pragma unroll
            for (int mt = 0; mt < 4; mt++)
                #pragma unroll
                for (int nt = 0; nt < 4; nt++) {
                    const int d = wn + nt * 8 + ccol;
                    #pragma unroll
                    for (int half = 0; half < 2; half++) {
                        const int gm = m0 + wm + mt * 16 + crow + half * 8;
                        vo[((size_t)hh * DH + d) * LL + gm] =
                            __float2bfloat16(acc[mt][nt][half * 2 + 0]);
                        vo[((size_t)hh * DH + d + 1) * LL + gm] =
                            __float2bfloat16(acc[mt][nt][half * 2 + 1]);
                    }
                }
        } else {
            float* rows = reinterpret_cast<float*>(smem);   // [4][128]
            __syncthreads();
            #pragma unroll
            for (int mt = 0; mt < 4; mt++) {
                #pragma unroll
                for (int half = 0; half < 2; half++) {
                    float ssum = 0.f;
                    #pragma unroll
                    for (int nt = 0; nt < 4; nt++) {
                        float a0 = acc[mt][nt][half * 2 + 0];
                        float a1 = acc[mt][nt][half * 2 + 1];
                        ssum += a0 * a0 + a1 * a1;
                    }
                    ssum += __shfl_xor_sync(0xffffffffu, ssum, 1);
                    ssum += __shfl_xor_sync(0xffffffffu, ssum, 2);
                    if ((lane & 3) == 0) {
                        const int lm = wm + mt * 16 + crow + half * 8;
                        rows[(warp & 3) * 128 + lm] = ssum;
                    }
                }
            }
            __syncthreads();
            __nv_bfloat16* dst = (type == 0) ? qo : ko;
            #pragma unroll
            for (int mt = 0; mt < 4; mt++) {
                #pragma unroll
                for (int half = 0; half < 2; half++) {
                    const int lm = wm + mt * 16 + crow + half * 8;
                    const int gm = m0 + lm;
                    const float tot = rows[lm] + rows[128 + lm]
                                    + rows[256 + lm] + rows[384 + lm];
                    const float rs = rsqrtf(tot * (1.f / DH) + 1e-6f);
                    const float* wn_ = (gm < LTXT) ? wqk_t : wqk_i;
                    #pragma unroll
                    for (int nt = 0; nt < 4; nt++) {
                        const int d = wn + nt * 8 + ccol;     // even
                        float ve = acc[mt][nt][half * 2 + 0] * rs * wn_[d];
                        float vodd = acc[mt][nt][half * 2 + 1] * rs * wn_[d + 1];
                        const float cth = pe[(size_t)gm * 256 + (d >> 1) * 4 + 0];
                        const float sth = pe[(size_t)gm * 256 + (d >> 1) * 4 + 2];
                        float r0 = ve * cth - vodd * sth;
                        float r1 = ve * sth + vodd * cth;
                        *reinterpret_cast<__nv_bfloat162*>(
                            &dst[((size_t)hh * LL + gm) * DH + d]) =
                            __nv_bfloat162(__float2bfloat16(r0), __float2bfloat16(r1));
                    }
                }
            }
        }
    } else {
        #pragma unroll
        for (int mt = 0; mt < 4; mt++) {
            #pragma unroll
            for (int nt = 0; nt < 4; nt++) {
                const int gn = n0 + wn + nt * 8 + ccol;
                #pragma unroll
                for (int half = 0; half < 2; half++) {
                    const int gm = m0 + wm + mt * 16 + crow + half * 8;
                    float v0 = acc[mt][nt][half * 2 + 0];
                    float v1 = acc[mt][nt][half * 2 + 1];
                    if (ACT == 1) {
                        v0 = fast_gelu(v0);
                        v1 = fast_gelu(v1);
                    }
                    const long long ci = (long long)gm * ldc + gn;
                    if (OUT == 0) {
                        *reinterpret_cast<float2*>(&C[ci]) = make_float2(v0, v1);
                    } else {
                        *reinterpret_cast<__nv_bfloat162*>(&Ch[ci]) =
                            __nv_bfloat162(__float2bfloat16(v0), __float2bfloat16(v1));
                    }
                }
            }
        }
    }
}

// ================= flash attention ==========================================
__global__ __launch_bounds__(128, 2)
void flash_kernel(const __nv_bfloat16* __restrict__ qg_,
                  const __nv_bfloat16* __restrict__ kg_,
                  const __nv_bfloat16* __restrict__ vg_,
                  __nv_bfloat16* __restrict__ o_)
{
    extern __shared__ __align__(128) char fsm[];
    const int tid = threadIdx.x, lane = tid & 31, warp = tid >> 5;
    const int qb = blockIdx.x, h = blockIdx.y;
    const char* qg = (const char*)(qg_ + ((size_t)h * LL + (size_t)qb * 64) * DH);
    const char* kg = (const char*)(kg_ + (size_t)h * LL * DH);
    const char* vg = (const char*)(vg_ + (size_t)h * DH * LL);
    const uint32_t sq = (uint32_t)__cvta_generic_to_shared(fsm);
    const uint32_t sk = sq + 17408u;
    const uint32_t sv = sq + 52224u;

    const int aRow = lane & 15;
    const int aK   = (lane & 16) ? 8 : 0;
    const int bRow = (lane & 7) + ((lane & 16) ? 8 : 0);
    const int bK   = (lane & 8) ? 8 : 0;
    const int g = lane >> 2, t4 = lane & 3;

    #pragma unroll
    for (int i = 0; i < 8; i++) {
        int idx = tid + i * 128;
        int row = idx >> 4, cb = (idx & 15) * 16;
        cpa(sq + (uint32_t)(row * 272 + cb), qg + row * 256 + cb);
    }
    asm volatile("cp.async.commit_group;" ::: "memory");

    float mv0 = -1e30f, mv1 = -1e30f, l0 = 0.f, l1 = 0.f;
    float oa[16][4];
    #pragma unroll
    for (int nt = 0; nt < 16; nt++) {
        oa[nt][0] = 0.f; oa[nt][1] = 0.f; oa[nt][2] = 0.f; oa[nt][3] = 0.f;
    }

    const float Cc = 0.12751781429348323f;  // (1/sqrt(128)) * log2(e)

    for (int kb = 0; kb < 16; kb++) {
        __syncthreads();
        #pragma unroll
        for (int i = 0; i < 16; i++) {
            int idx = tid + i * 128;
            int row = idx >> 4, cb = (idx & 15) * 16;
            cpa(sk + (uint32_t)(row * 272 + cb),
                kg + (size_t)(kb * 128 + row) * 256 + cb);
            cpa(sv + (uint32_t)(row * 272 + cb),
                vg + (size_t)row * 4096 + kb * 256 + cb);
        }
        asm volatile("cp.async.commit_group;" ::: "memory");
        asm volatile("cp.async.wait_group 0;" ::: "memory");
        __syncthreads();

        float sa[16][4];
        #pragma unroll
        for (int nt = 0; nt < 16; nt++) {
            sa[nt][0] = 0.f; sa[nt][1] = 0.f; sa[nt][2] = 0.f; sa[nt][3] = 0.f;
        }
        #pragma unroll
        for (int ks = 0; ks < 8; ks++) {
            uint32_t qf[4];
            ldsm4(qf, sq + (uint32_t)((warp * 16 + aRow) * 136 + ks * 16 + aK) * 2u);
            #pragma unroll
            for (int pr = 0; pr < 8; pr++) {
                uint32_t bf[4];
                ldsm4(bf, sk + (uint32_t)((pr * 16 + bRow) * 136 + ks * 16 + bK) * 2u);
                mma_bf16(sa[2 * pr],     qf, &bf[0]);
                mma_bf16(sa[2 * pr + 1], qf, &bf[2]);
            }
        }

        float rm0 = -1e30f, rm1 = -1e30f;
        #pragma unroll
        for (int nt = 0; nt < 16; nt++) {
            rm0 = fmaxf(rm0, fmaxf(sa[nt][0], sa[nt][1]));
            rm1 = fmaxf(rm1, fmaxf(sa[nt][2], sa[nt][3]));
        }
        rm0 = fmaxf(rm0, __shfl_xor_sync(0xffffffffu, rm0, 1));
        rm0 = fmaxf(rm0, __shfl_xor_sync(0xffffffffu, rm0, 2));
        rm1 = fmaxf(rm1, __shfl_xor_sync(0xffffffffu, rm1, 1));
        rm1 = fmaxf(rm1, __shfl_xor_sync(0xffffffffu, rm1, 2));
        const float mn0 = fmaxf(mv0, rm0), mn1 = fmaxf(mv1, rm1);
        const float r0 = ex2((mv0 - mn0) * Cc), r1 = ex2((mv1 - mn1) * Cc);
        mv0 = mn0; mv1 = mn1;

        float s0 = 0.f, s1 = 0.f;
        uint32_t pf[16], pg[16];
        #pragma unroll
        for (int nt = 0; nt < 16; nt++) {
            float p0 = ex2((sa[nt][0] - mn0) * Cc);
            float p1 = ex2((sa[nt][1] - mn0) * Cc);
            float p2 = ex2((sa[nt][2] - mn1) * Cc);
            float p3 = ex2((sa[nt][3] - mn1) * Cc);
            s0 += p0 + p1; s1 += p2 + p3;
            pf[nt] = packbf(p0, p1);
            pg[nt] = packbf(p2, p3);
        }
        s0 += __shfl_xor_sync(0xffffffffu, s0, 1);
        s0 += __shfl_xor_sync(0xffffffffu, s0, 2);
        s1 += __shfl_xor_sync(0xffffffffu, s1, 1);
        s1 += __shfl_xor_sync(0xffffffffu, s1, 2);
        l0 = l0 * r0 + s0;
        l1 = l1 * r1 + s1;
        #pragma unroll
        for (int nt = 0; nt < 16; nt++) {
            oa[nt][0] *= r0; oa[nt][1] *= r0;
            oa[nt][2] *= r1; oa[nt][3] *= r1;
        }

        #pragma unroll
        for (int ks = 0; ks < 8; ks++) {
            uint32_t af[4];
            af[0] = pf[2 * ks];     af[1] = pg[2 * ks];
            af[2] = pf[2 * ks + 1]; af[3] = pg[2 * ks + 1];
            #pragma unroll
            for (int pr = 0; pr < 8; pr++) {
                uint32_t bf[4];
                ldsm4(bf, sv + (uint32_t)((pr * 16 + bRow) * 136 + ks * 16 + bK) * 2u);
                mma_bf16(oa[2 * pr],     af, &bf[0]);
                mma_bf16(oa[2 * pr + 1], af, &bf[2]);
            }
        }
    }

    const float i0 = 1.f / l0, i1 = 1.f / l1;
    const int row0 = qb * 64 + warp * 16 + g;
    #pragma unroll
    for (int nt = 0; nt < 16; nt++) {
        const int col = h * DH + nt * 8 + 2 * t4;
        *reinterpret_cast<__nv_bfloat162*>(&o_[(size_t)row0 * DIM + col]) =
            __nv_bfloat162(__float2bfloat16(oa[nt][0] * i0),
                           __float2bfloat16(oa[nt][1] * i0));
        *reinterpret_cast<__nv_bfloat162*>(&o_[(size_t)(row0 + 8) * DIM + col]) =
            __nv_bfloat162(__float2bfloat16(oa[nt][2] * i1),
                           __float2bfloat16(oa[nt][3] * i1));
    }
}

// ---------------- LN + adaLN modulation -> bf16 ----------------
__global__ __launch_bounds__(256)
void lnmod_attn_kernel(const float* __restrict__ img_e, const float* __restrict__ txt_e,
                       const float* __restrict__ i_sc, const float* __restrict__ i_sh,
                       const float* __restrict__ t_sc, const float* __restrict__ t_sh,
                       __nv_bfloat16* __restrict__ oh)
{
    const int row = blockIdx.x;
    const bool is_txt = row < LTXT;
    const float* x  = is_txt ? txt_e + (size_t)row * DIM : img_e + (size_t)(row - LTXT) * DIM;
    const float* sc = is_txt ? t_sc : i_sc;
    const float* sh = is_txt ? t_sh : i_sh;
    __shared__ float red[8];
    const int tid = threadIdx.x;
    float v[12];
    float s = 0.f, ss = 0.f;
    #pragma unroll
    for (int i = 0; i < 12; i++) {
        float a = x[tid + i * 256];
        v[i] = a; s += a; ss += a * a;
    }
    s  = blk_sum<8>(s,  red);
    ss = blk_sum<8>(ss, red);
    const float m   = s * (1.f / DIM);
    const float var = ss * (1.f / DIM) - m * m;
    const float rs  = rsqrtf(var + 1e-6f);
    #pragma unroll
    for (int i = 0; i < 12; i++) {
        const int c = tid + i * 256;
        oh[(size_t)row * DIM + c] =
            __float2bfloat16((1.f + sc[c]) * (v[i] - m) * rs + sh[c]);
    }
}

// ---- attn residual (gated, 2-way split-K reduce + bias) + LN + MLP mod ----
__global__ __launch_bounds__(256)
void resid_lnmod_kernel(const float* __restrict__ part, const float* __restrict__ proj_b,
                        const float* __restrict__ img_e, const float* __restrict__ txt_e,
                        const float* __restrict__ i_gate, const float* __restrict__ t_gate,
                        const float* __restrict__ i_sc, const float* __restrict__ i_sh,
                        const float* __restrict__ t_sc, const float* __restrict__ t_sh,
                        float* __restrict__ resid, __nv_bfloat16* __restrict__ mih)
{
    const int row = blockIdx.x;
    const bool is_txt = row < LTXT;
    const float* e  = is_txt ? txt_e + (size_t)row * DIM : img_e + (size_t)(row - LTXT) * DIM;
    const float* g  = is_txt ? t_gate : i_gate;
    const float* sc = is_txt ? t_sc : i_sc;
    const float* sh = is_txt ? t_sh : i_sh;
    __shared__ float red[8];
    const int tid = threadIdx.x;
    const size_t PS = (size_t)LL * DIM;
    float r[12];
    float s = 0.f, ss = 0.f;
    #pragma unroll
    for (int i = 0; i < 12; i++) {
        const int c = tid + i * 256;
        const size_t idx = (size_t)row * DIM + c;
        float p = part[idx] + part[PS + idx] + proj_b[c];
        float x = e[c] + g[c] * p;
        r[i] = x; s += x; ss += x * x;
        resid[idx] = x;
    }
    s  = blk_sum<8>(s,  red);
    ss = blk_sum<8>(ss, red);
    const float m   = s * (1.f / DIM);
    const float var = ss * (1.f / DIM) - m * m;
    const float rs  = rsqrtf(var + 1e-6f);
    #pragma unroll
    for (int i = 0; i < 12; i++) {
        const int c = tid + i * 256;
        mih[(size_t)row * DIM + c] =
            __float2bfloat16((1.f + sc[c]) * (r[i] - m) * rs + sh[c]);
    }
}

// ---- final gated residual (2-way split-K reduce + bias) -> d_out ----
__global__ __launch_bounds__(256)
void final_kernel(const float* __restrict__ part,
                  const float* __restrict__ t_b2, const float* __restrict__ i_b2,
                  const float* __restrict__ resid,
                  const float* __restrict__ i_gate, const float* __restrict__ t_gate,
                  float* __restrict__ out)
{
    const int row = blockIdx.x;
    const int tid = threadIdx.x;
    const bool is_txt = row < LTXT;
    const float* g  = is_txt ? t_gate : i_gate;
    const float* b2 = is_txt ? t_b2 : i_b2;
    const size_t PS = (size_t)LL * DIM;
    float* dst = is_txt ? out + (size_t)LIMG * DIM + (size_t)row * DIM
                        : out + (size_t)(row - LTXT) * DIM;
    #pragma unroll
    for (int i = 0; i < 12; i++) {
        const int c = tid + i * 256;
        const size_t idx = (size_t)row * DIM + c;
        float mlp = part[idx] + part[PS + idx] + b2[c];
        dst[c] = resid[idx] + g[c] * mlp;
    }
}

// ---------------- launch ----------------
extern "C" void kernel_launch(void* const* d_in, const int* in_sizes, int n_in,
                              void* d_out, int out_size)
{
    const float* img_e       = (const float*)d_in[0];
    const float* txt_e       = (const float*)d_in[1];
    const float* pe          = (const float*)d_in[2];
    const float* i_attn_sc   = (const float*)d_in[3];
    const float* i_attn_sh   = (const float*)d_in[4];
    const float* i_attn_gate = (const float*)d_in[5];
    const float* i_mlp_sc    = (const float*)d_in[6];
    const float* i_mlp_sh    = (const float*)d_in[7];
    const float* i_mlp_gate  = (const float*)d_in[8];
    const float* t_attn_sc   = (const float*)d_in[9];
    const float* t_attn_sh   = (const float*)d_in[10];
    const float* t_attn_gate = (const float*)d_in[11];
    const float* t_mlp_sc    = (const float*)d_in[12];
    const float* t_mlp_sh    = (const float*)d_in[13];
    const float* t_mlp_gate  = (const float*)d_in[14];
    const float* i_qkv_w     = (const float*)d_in[15];
    const float* i_qkv_b     = (const float*)d_in[16];
    const float* i_qknorm    = (const float*)d_in[17];
    const float* t_qkv_w     = (const float*)d_in[18];
    const float* t_qkv_b     = (const float*)d_in[19];
    const float* t_qknorm    = (const float*)d_in[20];
    const float* proj_w      = (const float*)d_in[21];
    const float* proj_b      = (const float*)d_in[22];
    const float* i_mlp_w1    = (const float*)d_in[23];
    const float* i_mlp_b1    = (const float*)d_in[24];
    const float* i_mlp_w2    = (const float*)d_in[25];
    const float* i_mlp_b2    = (const float*)d_in[26];
    const float* t_mlp_w1    = (const float*)d_in[27];
    const float* t_mlp_b1    = (const float*)d_in[28];
    const float* t_mlp_w2    = (const float*)d_in[29];
    const float* t_mlp_b2    = (const float*)d_in[30];
    // d_in[31] = mask (all-true; unused)

    __nv_bfloat16 *xmh, *qh, *kh, *vth, *ath, *mih, *mhh;
    float *part, *resid;
    cudaGetSymbolAddress((void**)&xmh,   g_xmh);
    cudaGetSymbolAddress((void**)&qh,    g_qh);
    cudaGetSymbolAddress((void**)&kh,    g_kh);
    cudaGetSymbolAddress((void**)&vth,   g_vth);
    cudaGetSymbolAddress((void**)&ath,   g_ath);
    cudaGetSymbolAddress((void**)&part,  g_part);
    cudaGetSymbolAddress((void**)&resid, g_resid);
    cudaGetSymbolAddress((void**)&mih,   g_mih);
    cudaGetSymbolAddress((void**)&mhh,   g_mhh);

    const int GSMEM = 51200;
    const int FSMEM = 87040;
    cudaFuncSetAttribute(gemm_wf<0, 0>, cudaFuncAttributeMaxDynamicSharedMemorySize, GSMEM);
    cudaFuncSetAttribute(gemm_wf<1, 1>, cudaFuncAttributeMaxDynamicSharedMemorySize, GSMEM);
    cudaFuncSetAttribute(gemm_wf<2, 0>, cudaFuncAttributeMaxDynamicSharedMemorySize, GSMEM);
    cudaFuncSetAttribute(flash_kernel,  cudaFuncAttributeMaxDynamicSharedMemorySize, FSMEM);

    // 1) LN + attention modulation -> bf16
    lnmod_attn_kernel<<<LL, 256>>>(img_e, txt_e, i_attn_sc, i_attn_sh,
                                   t_attn_sc, t_attn_sh, xmh);

    // 2) QKV GEMM with fused bias + RMSNorm + RoPE + v-transpose epilogue
    gemm_wf<2, 0><<<dim3(3 * DIM / 128, LL / 128, 1), 256, GSMEM>>>(
        xmh, t_qkv_w, i_qkv_w, nullptr, nullptr, t_qkv_b, i_qkv_b,
        LTXT, DIM, DIM, DIM, 0, 0, 0, 0, 1.f,
        pe, t_qknorm, i_qknorm, qh, kh, vth);

    // 3) fused flash attention -> bf16 ath [l, h*DH+dh]
    flash_kernel<<<dim3(LL / 64, NH), 128, FSMEM>>>(qh, kh, vth, ath);

    // 4) shared projection, split-K=2 -> fp32 partials
    gemm_wf<0, 0><<<dim3(DIM / 128, LL / 128, 2), 256, GSMEM>>>(
        ath, proj_w, nullptr, part, nullptr, nullptr, nullptr,
        0, DIM / 2, DIM, DIM, DIM,
        (long long)(DIM / 2), (long long)(DIM / 2), (long long)LL * DIM, 1.f,
        nullptr, nullptr, nullptr, nullptr, nullptr, nullptr);

    // 5) gated attn residual (reduce 2 partials + bias) + LN + MLP modulation
    resid_lnmod_kernel<<<LL, 256>>>(part, proj_b, img_e, txt_e,
                                    i_attn_gate, t_attn_gate,
                                    i_mlp_sc, i_mlp_sh, t_mlp_sc, t_mlp_sh,
                                    resid, mih);

    // 6) MLP up (merged, bias+gelu fused) -> bf16 h
    gemm_wf<1, 1><<<dim3(MLPD / 128, LL / 128, 1), 256, GSMEM>>>(
        mih, t_mlp_w1, i_mlp_w1, nullptr, mhh, t_mlp_b1, i_mlp_b1,
        LTXT, DIM, DIM, DIM, MLPD, 0, 0, 0, 1.f,
        nullptr, nullptr, nullptr, nullptr, nullptr, nullptr);

    // 7) MLP down (merged, split-K=2) -> fp32 partials
    gemm_wf<0, 0><<<dim3(DIM / 128, LL / 128, 2), 256, GSMEM>>>(
        mhh, t_mlp_w2, i_mlp_w2, part, nullptr, nullptr, nullptr,
        LTXT, MLPD / 2, MLPD, MLPD, DIM,
        (long long)(MLPD / 2), (long long)(MLPD / 2), (long long)LL * DIM, 1.f,
        nullptr, nullptr, nullptr, nullptr, nullptr, nullptr);

    // 8) final gated residual (reduce 2 partials + bias) -> output
    final_kernel<<<LL, 256>>>(part, t_mlp_b2, i_mlp_b2, resid,
                              i_mlp_gate, t_mlp_gate, (float*)d_out);
}